// round 2
// baseline (speedup 1.0000x reference)
#include <cuda_runtime.h>
#include <math.h>

#define B_TOTAL 32768
#define H 64
#define E 16
#define NM 6
#define P 12
#define T 30
#define TPB 256
#define NBLK (B_TOTAL / TPB)

// shared-memory layout (float offsets), all float4-aligned where needed
#define OFF_WHH   0            // 256*64 = 16384
#define OFF_WIH   16384        // 256*16 = 4096
#define OFF_B     20480        // 256
#define OFF_WPOS  20736        // 12*64 = 768
#define OFF_BPOS  21504        // 16 (12 used)
#define OFF_WSE   21520        // 16*12 = 192
#define OFF_BSE   21712        // 16
#define OFF_WCONF 21728        // 6*64 = 384
#define OFF_BCONF 22112        // 16 (6 used)
#define OFF_C     22128        // 64*256 = 16384
#define OFF_HN    38512        // 64*256 = 16384
#define SMEM_FLOATS 54896
#define SMEM_BYTES (SMEM_FLOATS * 4)

#define CONF_BASE ((size_t)B_TOTAL * NM * T * 2)   // 11796480

__device__ __forceinline__ float sigmoidf_(float v) {
    return 1.0f / (1.0f + expf(-v));
}
__device__ __forceinline__ float lrelu_(float v) {
    return v > 0.0f ? v : 0.01f * v;
}

__global__ void __launch_bounds__(TPB, 1)
decoder_lstm_kernel(const float* __restrict__ traj_rel,
                    const float* __restrict__ h0,
                    const float* __restrict__ c0,
                    const float* __restrict__ W_ih,
                    const float* __restrict__ W_hh,
                    const float* __restrict__ b_ih,
                    const float* __restrict__ b_hh,
                    const float* __restrict__ W_se,
                    const float* __restrict__ b_se,
                    const float* __restrict__ W_pos,
                    const float* __restrict__ b_pos,
                    const float* __restrict__ W_conf,
                    const float* __restrict__ b_conf,
                    float* __restrict__ out)
{
    extern __shared__ float sm[];
    float* sWhh   = sm + OFF_WHH;
    float* sWih   = sm + OFF_WIH;
    float* sB     = sm + OFF_B;
    float* sWpos  = sm + OFF_WPOS;
    float* sBpos  = sm + OFF_BPOS;
    float* sWse   = sm + OFF_WSE;
    float* sBse   = sm + OFF_BSE;
    float* sWconf = sm + OFF_WCONF;
    float* sBconf = sm + OFF_BCONF;
    float* sC     = sm + OFF_C;
    float* sHN    = sm + OFF_HN;

    const int tid = threadIdx.x;

    // ---- stage weights to shared ----
    for (int i = tid; i < 256 * 64; i += TPB) sWhh[i] = W_hh[i];
    for (int i = tid; i < 256 * 16; i += TPB) sWih[i] = W_ih[i];
    if (tid < 256) sB[tid] = b_ih[tid] + b_hh[tid];
    for (int i = tid; i < 12 * 64; i += TPB) sWpos[i] = W_pos[i];
    if (tid < 12) sBpos[tid] = b_pos[tid];
    if (tid < 16 * 12) sWse[tid] = W_se[tid];
    if (tid < 16) sBse[tid] = b_se[tid];
    for (int i = tid; i < 6 * 64; i += TPB) sWconf[i] = W_conf[i];
    if (tid < 6) sBconf[tid] = b_conf[tid];
    __syncthreads();

    const int bagent = blockIdx.x * TPB + tid;

    // ---- per-agent state init ----
    const float rx = traj_rel[2 * bagent];
    const float ry = traj_rel[2 * bagent + 1];

    float x[E];
    #pragma unroll
    for (int e = 0; e < E; e++) {
        float s = sBse[e];
        #pragma unroll
        for (int p = 0; p < P; p++)
            s += ((p & 1) ? ry : rx) * sWse[e * P + p];
        x[e] = lrelu_(s);
    }

    float h[H];
    {
        const float4* h0v = (const float4*)(h0 + (size_t)bagent * H);
        #pragma unroll
        for (int k = 0; k < H / 4; k++) {
            float4 v = h0v[k];
            h[4 * k] = v.x; h[4 * k + 1] = v.y; h[4 * k + 2] = v.z; h[4 * k + 3] = v.w;
        }
        const float4* c0v = (const float4*)(c0 + (size_t)bagent * H);
        #pragma unroll
        for (int k = 0; k < H / 4; k++) {
            float4 v = c0v[k];
            sC[(4 * k + 0) * TPB + tid] = v.x;
            sC[(4 * k + 1) * TPB + tid] = v.y;
            sC[(4 * k + 2) * TPB + tid] = v.z;
            sC[(4 * k + 3) * TPB + tid] = v.w;
        }
    }

    float* outp = out + (size_t)bagent * (NM * T * 2);

    // ---- 30 sequential LSTM steps ----
    for (int t = 0; t < T; t++) {
        #pragma unroll 1
        for (int k = 0; k < H; k++) {
            float gi = sB[k];
            float gf = sB[64 + k];
            float gg = sB[128 + k];
            float go = sB[192 + k];

            const float* wi0 = sWih + k * 16;
            const float* wi1 = sWih + (64 + k) * 16;
            const float* wi2 = sWih + (128 + k) * 16;
            const float* wi3 = sWih + (192 + k) * 16;
            #pragma unroll
            for (int e = 0; e < E; e += 4) {
                float4 a = *(const float4*)(wi0 + e);
                float4 b4 = *(const float4*)(wi1 + e);
                float4 c4 = *(const float4*)(wi2 + e);
                float4 d4 = *(const float4*)(wi3 + e);
                gi += x[e] * a.x + x[e + 1] * a.y + x[e + 2] * a.z + x[e + 3] * a.w;
                gf += x[e] * b4.x + x[e + 1] * b4.y + x[e + 2] * b4.z + x[e + 3] * b4.w;
                gg += x[e] * c4.x + x[e + 1] * c4.y + x[e + 2] * c4.z + x[e + 3] * c4.w;
                go += x[e] * d4.x + x[e + 1] * d4.y + x[e + 2] * d4.z + x[e + 3] * d4.w;
            }

            const float* wh0 = sWhh + k * 64;
            const float* wh1 = sWhh + (64 + k) * 64;
            const float* wh2 = sWhh + (128 + k) * 64;
            const float* wh3 = sWhh + (192 + k) * 64;
            #pragma unroll
            for (int j = 0; j < H; j += 4) {
                float4 a = *(const float4*)(wh0 + j);
                float4 b4 = *(const float4*)(wh1 + j);
                float4 c4 = *(const float4*)(wh2 + j);
                float4 d4 = *(const float4*)(wh3 + j);
                gi += h[j] * a.x + h[j + 1] * a.y + h[j + 2] * a.z + h[j + 3] * a.w;
                gf += h[j] * b4.x + h[j + 1] * b4.y + h[j + 2] * b4.z + h[j + 3] * b4.w;
                gg += h[j] * c4.x + h[j + 1] * c4.y + h[j + 2] * c4.z + h[j + 3] * c4.w;
                go += h[j] * d4.x + h[j + 1] * d4.y + h[j + 2] * d4.z + h[j + 3] * d4.w;
            }

            float ti = sigmoidf_(gi);
            float tf = sigmoidf_(gf);
            float tg = tanhf(gg);
            float to = sigmoidf_(go);
            float cc = tf * sC[k * TPB + tid] + ti * tg;
            sC[k * TPB + tid] = cc;
            sHN[k * TPB + tid] = to * tanhf(cc);
        }

        // adopt new hidden state
        #pragma unroll
        for (int k = 0; k < H; k++) h[k] = sHN[k * TPB + tid];

        // rel = h @ W_pos^T + b_pos ; write pred slice ; x = lrelu(rel @ W_se^T + b_se)
        float rel[P];
        #pragma unroll
        for (int p = 0; p < P; p++) {
            float r = sBpos[p];
            #pragma unroll
            for (int j = 0; j < H; j += 4) {
                float4 w = *(const float4*)(sWpos + p * 64 + j);
                r += h[j] * w.x + h[j + 1] * w.y + h[j + 2] * w.z + h[j + 3] * w.w;
            }
            rel[p] = r;
            // pred[b, m, t, xy]  with p = m*2 + xy
            outp[(p >> 1) * (T * 2) + t * 2 + (p & 1)] = r;
        }

        #pragma unroll
        for (int e = 0; e < E; e++) {
            float s = sBse[e];
            #pragma unroll
            for (int p = 0; p < P; p++) s += rel[p] * sWse[e * P + p];
            x[e] = lrelu_(s);
        }
    }

    // ---- confidence head: softmax(h @ W_conf^T + b_conf) ----
    float lg[NM];
    #pragma unroll
    for (int m = 0; m < NM; m++) {
        float s = sBconf[m];
        #pragma unroll
        for (int j = 0; j < H; j++) s += h[j] * sWconf[m * 64 + j];
        lg[m] = s;
    }
    float mx = lg[0];
    #pragma unroll
    for (int m = 1; m < NM; m++) mx = fmaxf(mx, lg[m]);
    float den = 0.0f;
    #pragma unroll
    for (int m = 0; m < NM; m++) { lg[m] = expf(lg[m] - mx); den += lg[m]; }
    float inv = 1.0f / den;
    #pragma unroll
    for (int m = 0; m < NM; m++)
        out[CONF_BASE + (size_t)bagent * NM + m] = lg[m] * inv;
}

extern "C" void kernel_launch(void* const* d_in, const int* in_sizes, int n_in,
                              void* d_out, int out_size)
{
    // input order: 0 traj_abs (unused), 1 traj_rel, 2 h0, 3 c0, 4 W_ih, 5 W_hh,
    // 6 b_ih, 7 b_hh, 8 W_se, 9 b_se, 10 W_pos, 11 b_pos, 12 W_conf, 13 b_conf
    const float* traj_rel = (const float*)d_in[1];
    const float* h0       = (const float*)d_in[2];
    const float* c0       = (const float*)d_in[3];
    const float* W_ih     = (const float*)d_in[4];
    const float* W_hh     = (const float*)d_in[5];
    const float* b_ih     = (const float*)d_in[6];
    const float* b_hh     = (const float*)d_in[7];
    const float* W_se     = (const float*)d_in[8];
    const float* b_se     = (const float*)d_in[9];
    const float* W_pos    = (const float*)d_in[10];
    const float* b_pos    = (const float*)d_in[11];
    const float* W_conf   = (const float*)d_in[12];
    const float* b_conf   = (const float*)d_in[13];
    float* out = (float*)d_out;

    // Not a stream op — executes eagerly, never enters the captured graph.
    // Idempotent and deterministic; ignore the return value.
    (void)cudaFuncSetAttribute(decoder_lstm_kernel,
                               cudaFuncAttributeMaxDynamicSharedMemorySize,
                               SMEM_BYTES);

    decoder_lstm_kernel<<<NBLK, TPB, SMEM_BYTES>>>(
        traj_rel, h0, c0, W_ih, W_hh, b_ih, b_hh,
        W_se, b_se, W_pos, b_pos, W_conf, b_conf, out);
}

// round 3
// speedup vs baseline: 3.4620x; 3.4620x over previous
#include <cuda_runtime.h>
#include <math.h>

#define B_TOTAL 32768
#define NM 6
#define T 30
#define TPB 256
#define AB 128                    // agents per block (2 threads/agent)
#define NBLK (B_TOTAL / AB)       // 256

// shared layout (float offsets)
#define OFF_W     0               // 256 rows x 80 ([Whh row(64) | Wih row(16)]) = 20480
#define OFF_B     20480           // 256 combined bias
#define OFF_WPOS  20736           // 12x64 = 768
#define OFF_BPOS  21504           // 16 (12 used)
#define OFF_WSE   21520           // 16x12 = 192
#define OFF_BSE   21712           // 16
#define OFF_WCONF 21728           // 6x64 = 384
#define OFF_BCONF 22112           // 16 (6 used)
#define SMEM_FLOATS 22128
#define SMEM_BYTES (SMEM_FLOATS * 4)   // 88512 B

#define CONF_BASE ((size_t)B_TOTAL * NM * T * 2)

typedef unsigned long long u64_t;

// packed f32x2 fma: d = a*b + d  (SASS FFMA2; only reachable via PTX)
__device__ __forceinline__ void fma2(u64_t& d, u64_t a, u64_t b) {
    asm("fma.rn.f32x2 %0, %1, %2, %0;" : "+l"(d) : "l"(a), "l"(b));
}
__device__ __forceinline__ u64_t pack2(float lo, float hi) {
    u64_t r; asm("mov.b64 %0, {%1, %2};" : "=l"(r) : "f"(lo), "f"(hi)); return r;
}
__device__ __forceinline__ float hsum2(u64_t v) {
    float a, b; asm("mov.b64 {%0, %1}, %2;" : "=f"(a), "=f"(b) : "l"(v));
    return a + b;
}
__device__ __forceinline__ float frcp_(float x) {
    float r; asm("rcp.approx.f32 %0, %1;" : "=f"(r) : "f"(x)); return r;
}
__device__ __forceinline__ float fsig(float v)  { return frcp_(1.0f + __expf(-v)); }
__device__ __forceinline__ float ftanh(float v) { return fmaf(-2.0f, frcp_(__expf(2.0f * v) + 1.0f), 1.0f); }

__global__ void __launch_bounds__(TPB)
decoder_lstm_kernel(const float* __restrict__ traj_rel,
                    const float* __restrict__ h0,
                    const float* __restrict__ c0,
                    const float* __restrict__ W_ih,
                    const float* __restrict__ W_hh,
                    const float* __restrict__ b_ih,
                    const float* __restrict__ b_hh,
                    const float* __restrict__ W_se,
                    const float* __restrict__ b_se,
                    const float* __restrict__ W_pos,
                    const float* __restrict__ b_pos,
                    const float* __restrict__ W_conf,
                    const float* __restrict__ b_conf,
                    float* __restrict__ out)
{
    extern __shared__ float sm[];
    float* sW     = sm + OFF_W;
    float* sB     = sm + OFF_B;
    float* sWpos  = sm + OFF_WPOS;
    float* sBpos  = sm + OFF_BPOS;
    float* sWse   = sm + OFF_WSE;
    float* sBse   = sm + OFF_BSE;
    float* sWconf = sm + OFF_WCONF;
    float* sBconf = sm + OFF_BCONF;

    const int tid = threadIdx.x;

    // ---- stage weights: combined [Whh | Wih] rows of 80 ----
    for (int i = tid; i < 256 * 80; i += TPB) {
        int r = i / 80, c = i % 80;
        sW[i] = (c < 64) ? W_hh[r * 64 + c] : W_ih[r * 16 + (c - 64)];
    }
    if (tid < 256) sB[tid] = b_ih[tid] + b_hh[tid];
    for (int i = tid; i < 12 * 64; i += TPB) sWpos[i] = W_pos[i];
    if (tid < 12) sBpos[tid] = b_pos[tid];
    if (tid < 192) sWse[tid] = W_se[tid];
    if (tid < 16) sBse[tid] = b_se[tid];
    for (int i = tid; i < 384; i += TPB) sWconf[i] = W_conf[i];
    if (tid < 6) sBconf[tid] = b_conf[tid];
    __syncthreads();

    const int al = tid >> 1;       // local agent
    const int hf = tid & 1;        // parity half: cells k = 2i+hf
    const int agent = blockIdx.x * AB + al;

    // vh[0..31]  = h packed as (h[2j], h[2j+1])
    // vh[32..39] = x packed as (x[2m], x[2m+1])
    u64_t vh[40];
    float c_[32], hn[32];

    {   // h0 loads directly as packed pairs (8B aligned)
        const u64_t* hv = (const u64_t*)(h0 + (size_t)agent * 64);
        #pragma unroll
        for (int i = 0; i < 32; i++) vh[i] = hv[i];
        #pragma unroll
        for (int i = 0; i < 32; i++) c_[i] = c0[(size_t)agent * 64 + 2 * i + hf];
    }
    {   // initial x from traj_rel (rel12 = [rx,ry,rx,ry,...])
        float rx = traj_rel[2 * agent], ry = traj_rel[2 * agent + 1];
        float xs[16];
        #pragma unroll
        for (int e = 0; e < 16; e++) {
            float se = 0.f, so = 0.f;
            #pragma unroll
            for (int q = 0; q < 6; q++) { se += sWse[e * 12 + 2 * q]; so += sWse[e * 12 + 2 * q + 1]; }
            float s = sBse[e] + rx * se + ry * so;
            xs[e] = s > 0.f ? s : 0.01f * s;
        }
        #pragma unroll
        for (int m = 0; m < 8; m++) vh[32 + m] = pack2(xs[2 * m], xs[2 * m + 1]);
    }

    float* outp = out + (size_t)agent * (NM * T * 2);

    for (int t = 0; t < T; t++) {
        // ---- gates + state update for my 32 cells ----
        #pragma unroll 1
        for (int i = 0; i < 32; i++) {
            const int k = 2 * i + hf;
            const ulonglong2* w0 = (const ulonglong2*)(sW + k * 80);
            const ulonglong2* w1 = (const ulonglong2*)(sW + (64 + k) * 80);
            const ulonglong2* w2 = (const ulonglong2*)(sW + (128 + k) * 80);
            const ulonglong2* w3 = (const ulonglong2*)(sW + (192 + k) * 80);
            u64_t a0 = 0ull, a1 = 0ull, a2 = 0ull, a3 = 0ull;  // (0.f, 0.f)
            #pragma unroll
            for (int jj = 0; jj < 20; jj++) {
                ulonglong2 q0 = w0[jj], q1 = w1[jj], q2 = w2[jj], q3 = w3[jj];
                u64_t vA = vh[2 * jj], vB = vh[2 * jj + 1];
                fma2(a0, q0.x, vA); fma2(a0, q0.y, vB);
                fma2(a1, q1.x, vA); fma2(a1, q1.y, vB);
                fma2(a2, q2.x, vA); fma2(a2, q2.y, vB);
                fma2(a3, q3.x, vA); fma2(a3, q3.y, vB);
            }
            float gi = hsum2(a0) + sB[k];
            float gf = hsum2(a1) + sB[64 + k];
            float gg = hsum2(a2) + sB[128 + k];
            float go = hsum2(a3) + sB[192 + k];
            float cc = fsig(gf) * c_[i] + fsig(gi) * ftanh(gg);
            c_[i] = cc;
            hn[i] = fsig(go) * ftanh(cc);
        }

        // ---- exchange with partner lane, rebuild packed h ----
        #pragma unroll
        for (int i = 0; i < 32; i++) {
            float mine = hn[i];
            float oth  = __shfl_xor_sync(0xffffffffu, mine, 1);
            vh[i] = hf ? pack2(oth, mine) : pack2(mine, oth);
        }

        // ---- rel = h @ Wpos^T + bpos  (6 of 12 per thread, p = 2q+hf) ----
        float rl[6];
        #pragma unroll
        for (int q = 0; q < 6; q++) {
            const int p = 2 * q + hf;
            const u64_t* wp = (const u64_t*)(sWpos + p * 64);
            u64_t acc = 0ull;
            #pragma unroll
            for (int j = 0; j < 32; j++) fma2(acc, wp[j], vh[j]);
            float r = hsum2(acc) + sBpos[p];
            rl[q] = r;
            outp[q * 60 + t * 2 + hf] = r;    // pred[agent][m=q][t][xy=hf]
        }

        // ---- pair up rel across the two lanes ----
        u64_t rel2[6];
        #pragma unroll
        for (int q = 0; q < 6; q++) {
            float oth = __shfl_xor_sync(0xffffffffu, rl[q], 1);
            rel2[q] = hf ? pack2(oth, rl[q]) : pack2(rl[q], oth);
        }

        // ---- x = lrelu(rel @ Wse^T + bse) (duplicated on both lanes) ----
        float xs[16];
        #pragma unroll
        for (int e = 0; e < 16; e++) {
            const u64_t* we = (const u64_t*)(sWse + e * 12);
            u64_t acc = 0ull;
            #pragma unroll
            for (int q = 0; q < 6; q++) fma2(acc, we[q], rel2[q]);
            float s = hsum2(acc) + sBse[e];
            xs[e] = s > 0.f ? s : 0.01f * s;
        }
        #pragma unroll
        for (int m = 0; m < 8; m++) vh[32 + m] = pack2(xs[2 * m], xs[2 * m + 1]);
    }

    // ---- confidence head: softmax over 6 modes (3 per lane, m = 2q+hf) ----
    float lgo[3];
    #pragma unroll
    for (int q = 0; q < 3; q++) {
        const int m = 2 * q + hf;
        const u64_t* wc = (const u64_t*)(sWconf + m * 64);
        u64_t acc = 0ull;
        #pragma unroll
        for (int j = 0; j < 32; j++) fma2(acc, wc[j], vh[j]);
        lgo[q] = hsum2(acc) + sBconf[m];
    }
    float l[6];
    #pragma unroll
    for (int q = 0; q < 3; q++) {
        float oth = __shfl_xor_sync(0xffffffffu, lgo[q], 1);
        l[2 * q + hf] = lgo[q];
        l[2 * q + (hf ^ 1)] = oth;
    }
    float mx = l[0];
    #pragma unroll
    for (int m = 1; m < 6; m++) mx = fmaxf(mx, l[m]);
    float den = 0.f;
    #pragma unroll
    for (int m = 0; m < 6; m++) { l[m] = __expf(l[m] - mx); den += l[m]; }
    float inv = frcp_(den);
    #pragma unroll
    for (int q = 0; q < 3; q++)
        out[CONF_BASE + (size_t)agent * NM + 2 * q + hf] = l[2 * q + hf] * inv;
}

extern "C" void kernel_launch(void* const* d_in, const int* in_sizes, int n_in,
                              void* d_out, int out_size)
{
    // 0 traj_abs (unused), 1 traj_rel, 2 h0, 3 c0, 4 W_ih, 5 W_hh,
    // 6 b_ih, 7 b_hh, 8 W_se, 9 b_se, 10 W_pos, 11 b_pos, 12 W_conf, 13 b_conf
    const float* traj_rel = (const float*)d_in[1];
    const float* h0       = (const float*)d_in[2];
    const float* c0       = (const float*)d_in[3];
    const float* W_ih     = (const float*)d_in[4];
    const float* W_hh     = (const float*)d_in[5];
    const float* b_ih     = (const float*)d_in[6];
    const float* b_hh     = (const float*)d_in[7];
    const float* W_se     = (const float*)d_in[8];
    const float* b_se     = (const float*)d_in[9];
    const float* W_pos    = (const float*)d_in[10];
    const float* b_pos    = (const float*)d_in[11];
    const float* W_conf   = (const float*)d_in[12];
    const float* b_conf   = (const float*)d_in[13];
    float* out = (float*)d_out;

    (void)cudaFuncSetAttribute(decoder_lstm_kernel,
                               cudaFuncAttributeMaxDynamicSharedMemorySize,
                               SMEM_BYTES);

    decoder_lstm_kernel<<<NBLK, TPB, SMEM_BYTES>>>(
        traj_rel, h0, c0, W_ih, W_hh, b_ih, b_hh,
        W_se, b_se, W_pos, b_pos, W_conf, b_conf, out);
}

// round 5
// speedup vs baseline: 4.8022x; 1.3871x over previous
#include <cuda_runtime.h>
#include <math.h>

#define B_TOTAL 32768
#define NM 6
#define T 30
#define TPB 512
#define AB 256                    // agents per block (2 threads/agent)
#define NBLK (B_TOTAL / AB)       // 128  -> single wave on 148 SMs

// shared layout (float offsets)
#define OFF_W     0               // 256 rows x 80 ([Whh row(64) | Wih row(16)]) = 20480
#define OFF_B     20480           // 256 combined bias
#define OFF_WPOS  20736           // 12x64 = 768
#define OFF_BPOS  21504           // 16 (12 used)
#define OFF_WSE   21520           // 16x12 = 192
#define OFF_BSE   21712           // 16
#define OFF_WCONF 21728           // 6x64 = 384
#define OFF_BCONF 22112           // 16 (6 used)
#define OFF_C     22128           // AB x 66 = 16896
#define OFF_HN    39024           // AB x 66 = 16896  (u64-aligned)
#define SMEM_FLOATS 55920
#define SMEM_BYTES (SMEM_FLOATS * 4)   // 223680 B

#define AST 66                    // per-agent stride (floats) for c / hn

#define CONF_BASE ((size_t)B_TOTAL * NM * T * 2)

typedef unsigned long long u64_t;

// packed f32x2 fma: d = a*b + d  (SASS FFMA2; only reachable via PTX)
__device__ __forceinline__ void fma2(u64_t& d, u64_t a, u64_t b) {
    asm("fma.rn.f32x2 %0, %1, %2, %0;" : "+l"(d) : "l"(a), "l"(b));
}
__device__ __forceinline__ u64_t pack2(float lo, float hi) {
    u64_t r; asm("mov.b64 %0, {%1, %2};" : "=l"(r) : "f"(lo), "f"(hi)); return r;
}
__device__ __forceinline__ float hsum2(u64_t v) {
    float a, b; asm("mov.b64 {%0, %1}, %2;" : "=f"(a), "=f"(b) : "l"(v));
    return a + b;
}
__device__ __forceinline__ float frcp_(float x) {
    float r; asm("rcp.approx.f32 %0, %1;" : "=f"(r) : "f"(x)); return r;
}
__device__ __forceinline__ float fsig(float v)  { return frcp_(1.0f + __expf(-v)); }
__device__ __forceinline__ float ftanh(float v) { return fmaf(-2.0f, frcp_(__expf(2.0f * v) + 1.0f), 1.0f); }

__global__ void __launch_bounds__(TPB, 1)
decoder_lstm_kernel(const float* __restrict__ traj_rel,
                    const float* __restrict__ h0,
                    const float* __restrict__ c0,
                    const float* __restrict__ W_ih,
                    const float* __restrict__ W_hh,
                    const float* __restrict__ b_ih,
                    const float* __restrict__ b_hh,
                    const float* __restrict__ W_se,
                    const float* __restrict__ b_se,
                    const float* __restrict__ W_pos,
                    const float* __restrict__ b_pos,
                    const float* __restrict__ W_conf,
                    const float* __restrict__ b_conf,
                    float* __restrict__ out)
{
    extern __shared__ float sm[];
    float* sW     = sm + OFF_W;
    float* sB     = sm + OFF_B;
    float* sWpos  = sm + OFF_WPOS;
    float* sBpos  = sm + OFF_BPOS;
    float* sWse   = sm + OFF_WSE;
    float* sBse   = sm + OFF_BSE;
    float* sWconf = sm + OFF_WCONF;
    float* sBconf = sm + OFF_BCONF;
    float* sC     = sm + OFF_C;
    float* sHN    = sm + OFF_HN;

    const int tid = threadIdx.x;

    // ---- stage weights (all grid-stride: every element covered) ----
    for (int i = tid; i < 256 * 80; i += TPB) {
        int r = i / 80, c = i % 80;
        sW[i] = (c < 64) ? W_hh[r * 64 + c] : W_ih[r * 16 + (c - 64)];
    }
    if (tid < 256) sB[tid] = b_ih[tid] + b_hh[tid];
    for (int i = tid; i < 12 * 64; i += TPB) sWpos[i] = W_pos[i];
    if (tid < 12) sBpos[tid] = b_pos[tid];
    if (tid < 192) sWse[tid] = W_se[tid];
    if (tid < 16) sBse[tid] = b_se[tid];
    for (int i = tid; i < 384; i += TPB) sWconf[i] = W_conf[i];
    if (tid < 6) sBconf[tid] = b_conf[tid];

    const int al = tid >> 1;       // local agent (0..255)
    const int hf = tid & 1;        // parity half: cells k = 2i+hf
    const int agent = blockIdx.x * AB + al;

    // c0 into shared (conflict-free padded layout)
    {
        const float* cg = c0 + (size_t)agent * 64;
        #pragma unroll
        for (int i = 0; i < 32; i++) sC[al * AST + 2 * i + hf] = cg[2 * i + hf];
    }
    __syncthreads();

    // vh[0..31]  = h packed as (h[2j], h[2j+1]); vh[32..39] = x pairs
    u64_t vh[40];
    {
        const u64_t* hv = (const u64_t*)(h0 + (size_t)agent * 64);
        #pragma unroll
        for (int i = 0; i < 32; i++) vh[i] = hv[i];
    }
    {   // initial x from traj_rel (rel12 = [rx,ry,rx,ry,...])
        float rx = traj_rel[2 * agent], ry = traj_rel[2 * agent + 1];
        float xs[16];
        #pragma unroll
        for (int e = 0; e < 16; e++) {
            float se = 0.f, so = 0.f;
            #pragma unroll
            for (int q = 0; q < 6; q++) { se += sWse[e * 12 + 2 * q]; so += sWse[e * 12 + 2 * q + 1]; }
            float s = sBse[e] + rx * se + ry * so;
            xs[e] = s > 0.f ? s : 0.01f * s;
        }
        #pragma unroll
        for (int m = 0; m < 8; m++) vh[32 + m] = pack2(xs[2 * m], xs[2 * m + 1]);
    }

    float* outp = out + (size_t)agent * (NM * T * 2);
    float* myC  = sC + al * AST;
    float* myHN = sHN + al * AST;
    const u64_t* myHN2 = (const u64_t*)(sHN + al * AST);

    for (int t = 0; t < T; t++) {
        // ---- gates + state update for my 32 cells ----
        #pragma unroll 1
        for (int i = 0; i < 32; i++) {
            const int k = 2 * i + hf;
            const ulonglong2* w0 = (const ulonglong2*)(sW + k * 80);
            const ulonglong2* w1 = (const ulonglong2*)(sW + (64 + k) * 80);
            const ulonglong2* w2 = (const ulonglong2*)(sW + (128 + k) * 80);
            const ulonglong2* w3 = (const ulonglong2*)(sW + (192 + k) * 80);
            u64_t a0 = 0ull, a1 = 0ull, a2 = 0ull, a3 = 0ull;  // (0.f, 0.f)
            #pragma unroll
            for (int jj = 0; jj < 20; jj++) {
                ulonglong2 q0 = w0[jj], q1 = w1[jj], q2 = w2[jj], q3 = w3[jj];
                u64_t vA = vh[2 * jj], vB = vh[2 * jj + 1];
                fma2(a0, q0.x, vA); fma2(a0, q0.y, vB);
                fma2(a1, q1.x, vA); fma2(a1, q1.y, vB);
                fma2(a2, q2.x, vA); fma2(a2, q2.y, vB);
                fma2(a3, q3.x, vA); fma2(a3, q3.y, vB);
            }
            float gi = hsum2(a0) + sB[k];
            float gf = hsum2(a1) + sB[64 + k];
            float gg = hsum2(a2) + sB[128 + k];
            float go = hsum2(a3) + sB[192 + k];
            float cc = fsig(gf) * myC[k] + fsig(gi) * ftanh(gg);
            myC[k] = cc;
            myHN[k] = fsig(go) * ftanh(cc);
        }

        // partner's hn writes are warp-local; make them visible, reload packed
        __syncwarp();
        #pragma unroll
        for (int i = 0; i < 32; i++) vh[i] = myHN2[i];

        // ---- rel = h @ Wpos^T + bpos  (6 of 12 per thread, p = 2q+hf) ----
        float rl[6];
        #pragma unroll
        for (int q = 0; q < 6; q++) {
            const int p = 2 * q + hf;
            const u64_t* wp = (const u64_t*)(sWpos + p * 64);
            u64_t acc = 0ull;
            #pragma unroll
            for (int j = 0; j < 32; j++) fma2(acc, wp[j], vh[j]);
            float r = hsum2(acc) + sBpos[p];
            rl[q] = r;
            outp[q * 60 + t * 2 + hf] = r;    // pred[agent][m=q][t][xy=hf]
        }

        // ---- pair up rel across the two lanes ----
        u64_t rel2[6];
        #pragma unroll
        for (int q = 0; q < 6; q++) {
            float oth = __shfl_xor_sync(0xffffffffu, rl[q], 1);
            rel2[q] = hf ? pack2(oth, rl[q]) : pack2(rl[q], oth);
        }

        // ---- x = lrelu(rel @ Wse^T + bse) (duplicated on both lanes) ----
        float xs[16];
        #pragma unroll
        for (int e = 0; e < 16; e++) {
            const u64_t* we = (const u64_t*)(sWse + e * 12);
            u64_t acc = 0ull;
            #pragma unroll
            for (int q = 0; q < 6; q++) fma2(acc, we[q], rel2[q]);
            float s = hsum2(acc) + sBse[e];
            xs[e] = s > 0.f ? s : 0.01f * s;
        }
        #pragma unroll
        for (int m = 0; m < 8; m++) vh[32 + m] = pack2(xs[2 * m], xs[2 * m + 1]);
    }

    // ---- confidence head: softmax over 6 modes (3 per lane, m = 2q+hf) ----
    float lgo[3];
    #pragma unroll
    for (int q = 0; q < 3; q++) {
        const int m = 2 * q + hf;
        const u64_t* wc = (const u64_t*)(sWconf + m * 64);
        u64_t acc = 0ull;
        #pragma unroll
        for (int j = 0; j < 32; j++) fma2(acc, wc[j], vh[j]);
        lgo[q] = hsum2(acc) + sBconf[m];
    }
    float l[6];
    #pragma unroll
    for (int q = 0; q < 3; q++) {
        float oth = __shfl_xor_sync(0xffffffffu, lgo[q], 1);
        l[2 * q + hf] = lgo[q];
        l[2 * q + (hf ^ 1)] = oth;
    }
    float mx = l[0];
    #pragma unroll
    for (int m = 1; m < 6; m++) mx = fmaxf(mx, l[m]);
    float den = 0.f;
    #pragma unroll
    for (int m = 0; m < 6; m++) { l[m] = __expf(l[m] - mx); den += l[m]; }
    float inv = frcp_(den);
    #pragma unroll
    for (int q = 0; q < 3; q++)
        out[CONF_BASE + (size_t)agent * NM + 2 * q + hf] = l[2 * q + hf] * inv;
}

extern "C" void kernel_launch(void* const* d_in, const int* in_sizes, int n_in,
                              void* d_out, int out_size)
{
    // 0 traj_abs (unused), 1 traj_rel, 2 h0, 3 c0, 4 W_ih, 5 W_hh,
    // 6 b_ih, 7 b_hh, 8 W_se, 9 b_se, 10 W_pos, 11 b_pos, 12 W_conf, 13 b_conf
    const float* traj_rel = (const float*)d_in[1];
    const float* h0       = (const float*)d_in[2];
    const float* c0       = (const float*)d_in[3];
    const float* W_ih     = (const float*)d_in[4];
    const float* W_hh     = (const float*)d_in[5];
    const float* b_ih     = (const float*)d_in[6];
    const float* b_hh     = (const float*)d_in[7];
    const float* W_se     = (const float*)d_in[8];
    const float* b_se     = (const float*)d_in[9];
    const float* W_pos    = (const float*)d_in[10];
    const float* b_pos    = (const float*)d_in[11];
    const float* W_conf   = (const float*)d_in[12];
    const float* b_conf   = (const float*)d_in[13];
    float* out = (float*)d_out;

    (void)cudaFuncSetAttribute(decoder_lstm_kernel,
                               cudaFuncAttributeMaxDynamicSharedMemorySize,
                               SMEM_BYTES);

    decoder_lstm_kernel<<<NBLK, TPB, SMEM_BYTES>>>(
        traj_rel, h0, c0, W_ih, W_hh, b_ih, b_hh,
        W_se, b_se, W_pos, b_pos, W_conf, b_conf, out);
}